// round 1
// baseline (speedup 1.0000x reference)
#include <cuda_runtime.h>
#include <cstdint>

#define BB 64
#define SS 512
#define HH 768
#define LL 9
#define NROWS (BB*SS)

// Scratch for emissions (natural-log domain), 64*512*9 floats = 4.7 MB
static __device__ float g_emis[NROWS * LL];

__device__ __forceinline__ float ex2f(float x) {
    float y;
    asm("ex2.approx.ftz.f32 %0, %1;" : "=f"(y) : "f"(x));
    return y;
}

// ---------------------------------------------------------------------------
// Kernel 1: emissions[r, l] = hidden[r, :] @ W[:, l] + b[l]
// One thread per row (b,s). W transposed into shared [L][H] so each inner
// access is a warp-uniform LDS.128 broadcast. Hidden read is per-lane
// sequential float4 (L1 line reuse makes it effectively coalesced).
// Also zeroes the output scalar.
// ---------------------------------------------------------------------------
__global__ __launch_bounds__(256) void emis_kernel(
    const float* __restrict__ hid,   // [B,S,H]
    const float* __restrict__ W,     // [H,L]
    const float* __restrict__ bias,  // [L]
    float* __restrict__ out)
{
    __shared__ __align__(16) float Ws[LL][HH];
    int tid = threadIdx.x;

    for (int idx = tid; idx < HH * LL; idx += blockDim.x) {
        int h = idx / LL, l = idx % LL;
        Ws[l][h] = W[idx];
    }
    if (blockIdx.x == 0 && tid == 0) out[0] = 0.0f;
    __syncthreads();

    int r = blockIdx.x * blockDim.x + tid;
    if (r >= NROWS) return;

    float acc[LL];
#pragma unroll
    for (int l = 0; l < LL; l++) acc[l] = bias[l];

    const float4* hp = reinterpret_cast<const float4*>(hid + (size_t)r * HH);
#pragma unroll 2
    for (int h4 = 0; h4 < HH / 4; h4++) {
        float4 x = hp[h4];
#pragma unroll
        for (int l = 0; l < LL; l++) {
            float4 w = reinterpret_cast<const float4*>(Ws[l])[h4];
            acc[l] += x.x * w.x + x.y * w.y + x.z * w.z + x.w * w.w;
        }
    }

    float* ep = g_emis + (size_t)r * LL;
#pragma unroll
    for (int l = 0; l < LL; l++) ep[l] = acc[l];
}

// ---------------------------------------------------------------------------
// Kernel 2: per-batch CRF forward scan (warp 0) + numerator (warp 1).
// Warp 0: lanes 0..8 hold alpha[j] (log2 domain). Per step:
//   broadcast alpha via SHFL, max-tree, 9x EX2, sum-tree, LG2.
// Warp 1: strided gather of emissions/transitions for the numerator.
// Block writes atomicAdd(out, denom - num).
// ---------------------------------------------------------------------------
__global__ __launch_bounds__(64) void crf_kernel(
    const int*   __restrict__ mask,        // [B,S]
    const int*   __restrict__ labels,      // [B,S]
    const float* __restrict__ start_trans, // [L]
    const float* __restrict__ end_trans,   // [L]
    const float* __restrict__ trans,       // [L,L]
    float* __restrict__ out)
{
    __shared__ float sh_denom, sh_num;
    const int b    = blockIdx.x;
    const int wid  = threadIdx.x >> 5;
    const int lane = threadIdx.x & 31;
    const float LOG2E  = 1.4426950408889634f;
    const float LN2    = 0.6931471805599453f;

    if (wid == 0) {
        const int j = (lane < LL) ? lane : (LL - 1);  // clamp for safe loads
        // T2[i] = trans[i][j] * log2(e), resident in registers
        float T2[LL];
#pragma unroll
        for (int i = 0; i < LL; i++) T2[i] = trans[i * LL + j] * LOG2E;

        const float* em = g_emis + (size_t)b * SS * LL;

        float alpha   = (start_trans[j] + em[j]) * LOG2E;
        float em_nat  = em[LL + j];              // emissions for t=1 (prefetch)
        int   mk_cur  = mask[b * SS + 1];

        for (int t = 1; t < SS; t++) {
            float em2 = em_nat * LOG2E;
            int   mk  = mk_cur;
            if (t + 1 < SS) {                    // prefetch next step
                em_nat = em[(t + 1) * LL + j];
                mk_cur = mask[b * SS + t + 1];
            }
            // broadcast alpha[0..8] to all lanes
            float v[LL];
#pragma unroll
            for (int i = 0; i < LL; i++)
                v[i] = __shfl_sync(0xFFFFFFFFu, alpha, i);
            // max over alpha (tree); trans adds are bounded so this is a
            // safe scaling constant
            float m01 = fmaxf(v[0], v[1]), m23 = fmaxf(v[2], v[3]);
            float m45 = fmaxf(v[4], v[5]), m67 = fmaxf(v[6], v[7]);
            float m = fmaxf(fmaxf(fmaxf(m01, m23), fmaxf(m45, m67)), v[8]);

            float e0 = ex2f(v[0] - m + T2[0]);
            float e1 = ex2f(v[1] - m + T2[1]);
            float e2 = ex2f(v[2] - m + T2[2]);
            float e3 = ex2f(v[3] - m + T2[3]);
            float e4 = ex2f(v[4] - m + T2[4]);
            float e5 = ex2f(v[5] - m + T2[5]);
            float e6 = ex2f(v[6] - m + T2[6]);
            float e7 = ex2f(v[7] - m + T2[7]);
            float e8 = ex2f(v[8] - m + T2[8]);
            float s = ((e0 + e1) + (e2 + e3)) + ((e4 + e5) + ((e6 + e7) + e8));

            float na = em2 + m + __log2f(s);
            alpha = mk ? na : alpha;
        }

        // denom = logsumexp(alpha + end_trans) in natural log
        float x = alpha + end_trans[j] * LOG2E;
        float v[LL];
#pragma unroll
        for (int i = 0; i < LL; i++)
            v[i] = __shfl_sync(0xFFFFFFFFu, x, i);
        float m01 = fmaxf(v[0], v[1]), m23 = fmaxf(v[2], v[3]);
        float m45 = fmaxf(v[4], v[5]), m67 = fmaxf(v[6], v[7]);
        float m = fmaxf(fmaxf(fmaxf(m01, m23), fmaxf(m45, m67)), v[8]);
        float s = 0.0f;
#pragma unroll
        for (int i = 0; i < LL; i++) s += ex2f(v[i] - m);
        if (lane == 0) sh_denom = (m + __log2f(s)) * LN2;
    }
    else {  // wid == 1 : numerator
        float part = 0.0f;
        int   cnt  = 0;
        for (int s0 = lane; s0 < SS; s0 += 32) {
            int   mk = mask[b * SS + s0];
            cnt += mk;
            int   l  = labels[b * SS + s0];
            float et = g_emis[((size_t)b * SS + s0) * LL + l];
            if (s0 == 0) {
                part += start_trans[l] + et;
            } else {
                int lp = labels[b * SS + s0 - 1];
                part += (trans[lp * LL + l] + et) * (float)mk;
            }
        }
#pragma unroll
        for (int o = 16; o > 0; o >>= 1) {
            part += __shfl_down_sync(0xFFFFFFFFu, part, o);
            cnt  += __shfl_down_sync(0xFFFFFFFFu, cnt,  o);
        }
        if (lane == 0) {
            int li = cnt - 1; if (li < 0) li = 0;
            int lt = labels[b * SS + li];
            sh_num = part + end_trans[lt];
        }
    }

    __syncthreads();
    if (threadIdx.x == 0) atomicAdd(out, sh_denom - sh_num);
}

// ---------------------------------------------------------------------------
// Launch: inputs in metadata order:
// 0 hidden_states f32 [64,512,768]
// 1 attention_mask i32 [64,512]
// 2 labels i32 [64,512]
// 3 W f32 [768,9]
// 4 b f32 [9]
// 5 start_trans f32 [9]
// 6 end_trans f32 [9]
// 7 trans f32 [9,9]
// out: scalar f32
// ---------------------------------------------------------------------------
extern "C" void kernel_launch(void* const* d_in, const int* in_sizes, int n_in,
                              void* d_out, int out_size)
{
    const float* hid    = (const float*)d_in[0];
    const int*   amask  = (const int*)  d_in[1];
    const int*   labels = (const int*)  d_in[2];
    const float* W      = (const float*)d_in[3];
    const float* bias   = (const float*)d_in[4];
    const float* st     = (const float*)d_in[5];
    const float* et     = (const float*)d_in[6];
    const float* tr     = (const float*)d_in[7];
    float* out = (float*)d_out;

    emis_kernel<<<NROWS / 256, 256>>>(hid, W, bias, out);
    crf_kernel<<<BB, 64>>>(amask, labels, st, et, tr, out);
}

// round 3
// speedup vs baseline: 1.0623x; 1.0623x over previous
#include <cuda_runtime.h>
#include <cstdint>

#define BB 64
#define SS 512
#define HH 768
#define LL 9
#define NROWS (BB*SS)

#define NCH 16          // chunks per batch
#define CHL 32          // steps per chunk

// emissions (natural-log domain): 64*512*9 floats = 4.7 MB
static __device__ float g_emis[NROWS * LL];
// per-chunk 9x9 linear matrices + log2-scale: 64*16*84 floats
static __device__ float g_mats[BB * NCH * 84];

#define LOG2E 1.4426950408889634f
#define LN2   0.6931471805599453f

// ---------------------------------------------------------------------------
// Kernel 1: emissions GEMM, smem-staged for coalescing.
// 128 threads/block, 2 rows/thread, 256 rows/block, 128 blocks.
// ---------------------------------------------------------------------------
#define EB 128
#define ROWS_PB 256
#define XS_STRIDE 258                       // even (float2-aligned), conflict-light
#define SM_X (32 * XS_STRIDE)               // 8256 floats
#define SM_W (HH * 12)                      // 9216 floats (9 padded to 12)
#define EMIS_SMEM ((SM_X + SM_W) * 4)       // 69,888 bytes

extern __shared__ float sm[];

__global__ __launch_bounds__(EB) void emis_kernel(
    const float* __restrict__ hid,
    const float* __restrict__ W,
    const float* __restrict__ bias,
    float* __restrict__ out)
{
    float* Xs = sm;            // [32][XS_STRIDE]
    float* Wt = sm + SM_X;     // [768][12]
    const int tid = threadIdx.x;

    for (int idx = tid; idx < HH * LL; idx += EB) {
        int h = idx / LL, j = idx - h * LL;
        Wt[h * 12 + j] = W[idx];
    }
    if (blockIdx.x == 0 && tid == 0) out[0] = 0.0f;

    const int r0 = blockIdx.x * ROWS_PB;
    float acc0[LL], acc1[LL];
#pragma unroll
    for (int j = 0; j < LL; j++) { acc0[j] = bias[j]; acc1[j] = bias[j]; }

    for (int hc = 0; hc < HH; hc += 32) {
        __syncthreads();   // Xs free to overwrite (also covers Wt on iter 0)
        // stage 256 rows x 32 h, coalesced float4 loads, transposed store
#pragma unroll
        for (int k2 = 0; k2 < 16; k2++) {
            int f = tid + k2 * EB;          // 0..2047
            int row = f >> 3, h4 = f & 7;
            float4 v = *reinterpret_cast<const float4*>(
                hid + (size_t)(r0 + row) * HH + hc + 4 * h4);
            Xs[(4*h4 + 0) * XS_STRIDE + row] = v.x;
            Xs[(4*h4 + 1) * XS_STRIDE + row] = v.y;
            Xs[(4*h4 + 2) * XS_STRIDE + row] = v.z;
            Xs[(4*h4 + 3) * XS_STRIDE + row] = v.w;
        }
        __syncthreads();

#pragma unroll
        for (int h = 0; h < 32; h++) {
            float2 x = *reinterpret_cast<const float2*>(Xs + h * XS_STRIDE + 2 * tid);
            const float4* wp = reinterpret_cast<const float4*>(Wt + (hc + h) * 12);
            float4 w0 = wp[0], w1 = wp[1], w2 = wp[2];
            acc0[0] = fmaf(x.x, w0.x, acc0[0]); acc1[0] = fmaf(x.y, w0.x, acc1[0]);
            acc0[1] = fmaf(x.x, w0.y, acc0[1]); acc1[1] = fmaf(x.y, w0.y, acc1[1]);
            acc0[2] = fmaf(x.x, w0.z, acc0[2]); acc1[2] = fmaf(x.y, w0.z, acc1[2]);
            acc0[3] = fmaf(x.x, w0.w, acc0[3]); acc1[3] = fmaf(x.y, w0.w, acc1[3]);
            acc0[4] = fmaf(x.x, w1.x, acc0[4]); acc1[4] = fmaf(x.y, w1.x, acc1[4]);
            acc0[5] = fmaf(x.x, w1.y, acc0[5]); acc1[5] = fmaf(x.y, w1.y, acc1[5]);
            acc0[6] = fmaf(x.x, w1.z, acc0[6]); acc1[6] = fmaf(x.y, w1.z, acc1[6]);
            acc0[7] = fmaf(x.x, w1.w, acc0[7]); acc1[7] = fmaf(x.y, w1.w, acc1[7]);
            acc0[8] = fmaf(x.x, w2.x, acc0[8]); acc1[8] = fmaf(x.y, w2.x, acc1[8]);
        }
    }

    const int rA = r0 + 2 * tid, rB = rA + 1;
    float* eA = g_emis + (size_t)rA * LL;
    float* eB = g_emis + (size_t)rB * LL;
#pragma unroll
    for (int j = 0; j < LL; j++) { eA[j] = acc0[j]; eB[j] = acc1[j]; }
}

// ---------------------------------------------------------------------------
// Kernel 2: per-chunk 9x9 transition-matrix product in linear domain.
// 27 active lanes: lane l -> row i=l/3, cols {3*(l%3) .. +2}.
// ---------------------------------------------------------------------------
__device__ __forceinline__ void rescale3(float& a0, float& a1, float& a2, float& sc)
{
    float mx = fmaxf(fmaxf(a0, a1), a2);
#pragma unroll
    for (int o = 16; o > 0; o >>= 1)
        mx = fmaxf(mx, __shfl_xor_sync(0xFFFFFFFFu, mx, o));
    int ex = (__float_as_int(mx) >> 23) - 127;
    float s = __int_as_float((127 - ex) << 23);
    a0 *= s; a1 *= s; a2 *= s;
    sc += (float)ex;
}

__global__ __launch_bounds__(32) void chunk_kernel(
    const int*   __restrict__ mask,
    const float* __restrict__ trans)
{
    const int b = blockIdx.y, c = blockIdx.x;
    const int lane = threadIdx.x;
    const int l = (lane < 27) ? lane : 26;
    const int i  = l / 3;
    const int jb = 3 * (l - 3 * i);     // column base (0,3,6)

    float ET0[LL], ET1[LL], ET2[LL];
#pragma unroll
    for (int k = 0; k < LL; k++) {
        ET0[k] = __expf(trans[k * LL + jb + 0]);
        ET1[k] = __expf(trans[k * LL + jb + 1]);
        ET2[k] = __expf(trans[k * LL + jb + 2]);
    }

    float a0 = (i == jb + 0) ? 1.0f : 0.0f;
    float a1 = (i == jb + 1) ? 1.0f : 0.0f;
    float a2 = (i == jb + 2) ? 1.0f : 0.0f;
    float sc = 0.0f;

    const int t0 = c * CHL;
    const int ts = (c == 0) ? 1 : t0;
    const int te = t0 + CHL;
    const float* em = g_emis + (size_t)b * SS * LL;
    const int*   mp = mask + b * SS;

    float e0 = em[ts * LL + jb], e1 = em[ts * LL + jb + 1], e2 = em[ts * LL + jb + 2];
    int mk = mp[ts];
    int cnt = 0;

    for (int t = ts; t < te; t++) {
        float f0 = __expf(e0), f1 = __expf(e1), f2 = __expf(e2);
        int m = mk;
        if (t + 1 < te) {
            e0 = em[(t+1) * LL + jb]; e1 = em[(t+1) * LL + jb + 1]; e2 = em[(t+1) * LL + jb + 2];
            mk = mp[t + 1];
        }
        // gather row i of A: row[3q+r] held by lane 3i+q, register r
        float r0 = __shfl_sync(0xFFFFFFFFu, a0, 3*i    );
        float r1 = __shfl_sync(0xFFFFFFFFu, a1, 3*i    );
        float r2 = __shfl_sync(0xFFFFFFFFu, a2, 3*i    );
        float r3 = __shfl_sync(0xFFFFFFFFu, a0, 3*i + 1);
        float r4 = __shfl_sync(0xFFFFFFFFu, a1, 3*i + 1);
        float r5 = __shfl_sync(0xFFFFFFFFu, a2, 3*i + 1);
        float r6 = __shfl_sync(0xFFFFFFFFu, a0, 3*i + 2);
        float r7 = __shfl_sync(0xFFFFFFFFu, a1, 3*i + 2);
        float r8 = __shfl_sync(0xFFFFFFFFu, a2, 3*i + 2);

        float n0 = r0*ET0[0] + r1*ET0[1]; n0 += r2*ET0[2] + r3*ET0[3];
        n0 += r4*ET0[4] + r5*ET0[5];      n0 += r6*ET0[6] + r7*ET0[7] + r8*ET0[8];
        float n1 = r0*ET1[0] + r1*ET1[1]; n1 += r2*ET1[2] + r3*ET1[3];
        n1 += r4*ET1[4] + r5*ET1[5];      n1 += r6*ET1[6] + r7*ET1[7] + r8*ET1[8];
        float n2 = r0*ET2[0] + r1*ET2[1]; n2 += r2*ET2[2] + r3*ET2[3];
        n2 += r4*ET2[4] + r5*ET2[5];      n2 += r6*ET2[6] + r7*ET2[7] + r8*ET2[8];
        n0 *= f0; n1 *= f1; n2 *= f2;

        a0 = m ? n0 : a0;  a1 = m ? n1 : a1;  a2 = m ? n2 : a2;

        if (((++cnt) & 7) == 0) rescale3(a0, a1, a2, sc);
    }

    rescale3(a0, a1, a2, sc);   // normalize before store

    float* mb = g_mats + (size_t)(b * NCH + c) * 84;
    if (lane < 27) {
        mb[i * LL + jb + 0] = a0;
        mb[i * LL + jb + 1] = a1;
        mb[i * LL + jb + 2] = a2;
    }
    if (lane == 0) mb[81] = sc;
}

// ---------------------------------------------------------------------------
// Kernel 3: per-batch fold of 16 chunk matrices (warp 0) + numerator (warp 1).
// ---------------------------------------------------------------------------
__global__ __launch_bounds__(64) void combine_kernel(
    const int*   __restrict__ mask,
    const int*   __restrict__ labels,
    const float* __restrict__ start_trans,
    const float* __restrict__ end_trans,
    const float* __restrict__ trans,
    float* __restrict__ out)
{
    __shared__ float sh_denom, sh_num;
    const int b = blockIdx.x;
    const int wid = threadIdx.x >> 5;
    const int lane = threadIdx.x & 31;

    if (wid == 0) {
        const int j = (lane < LL) ? lane : (LL - 1);
        const float* em = g_emis + (size_t)b * SS * LL;

        float a = start_trans[j] + em[j];           // natural log, t=0
        float mx = a;
#pragma unroll
        for (int o = 16; o > 0; o >>= 1)
            mx = fmaxf(mx, __shfl_xor_sync(0xFFFFFFFFu, mx, o));
        float v  = __expf(a - mx);                  // linear
        float sc = mx * LOG2E;                      // scale tracked in log2

        for (int c = 0; c < NCH; c++) {
            const float* mb = g_mats + (size_t)(b * NCH + c) * 84;
            float col[LL];
#pragma unroll
            for (int i2 = 0; i2 < LL; i2++) col[i2] = mb[i2 * LL + j];
            float msc = mb[81];

            float n = 0.0f;
#pragma unroll
            for (int i2 = 0; i2 < LL; i2++) {
                float vv = __shfl_sync(0xFFFFFFFFu, v, i2);
                n = fmaf(vv, col[i2], n);
            }
            sc += msc;
            // renormalize
            float m2 = n;
#pragma unroll
            for (int o = 16; o > 0; o >>= 1)
                m2 = fmaxf(m2, __shfl_xor_sync(0xFFFFFFFFu, m2, o));
            int ex = (__float_as_int(m2) >> 23) - 127;
            n *= __int_as_float((127 - ex) << 23);
            sc += (float)ex;
            v = n;
        }

        float x = v * __expf(end_trans[j]);
        if (lane >= LL) x = 0.0f;
#pragma unroll
        for (int o = 16; o > 0; o >>= 1)
            x += __shfl_xor_sync(0xFFFFFFFFu, x, o);
        if (lane == 0) sh_denom = (sc + __log2f(x)) * LN2;
    }
    else {  // numerator
        float part = 0.0f;
        int   cnt  = 0;
        for (int s0 = lane; s0 < SS; s0 += 32) {
            int   mk = mask[b * SS + s0];
            cnt += mk;
            int   lb = labels[b * SS + s0];
            float et = g_emis[((size_t)b * SS + s0) * LL + lb];
            if (s0 == 0) {
                part += start_trans[lb] + et;
            } else {
                int lp = labels[b * SS + s0 - 1];
                part += (trans[lp * LL + lb] + et) * (float)mk;
            }
        }
#pragma unroll
        for (int o = 16; o > 0; o >>= 1) {
            part += __shfl_down_sync(0xFFFFFFFFu, part, o);
            cnt  += __shfl_down_sync(0xFFFFFFFFu, cnt,  o);
        }
        if (lane == 0) {
            int li = cnt - 1; if (li < 0) li = 0;
            int lt = labels[b * SS + li];
            sh_num = part + end_trans[lt];
        }
    }

    __syncthreads();
    if (threadIdx.x == 0) atomicAdd(out, sh_denom - sh_num);
}

// ---------------------------------------------------------------------------
extern "C" void kernel_launch(void* const* d_in, const int* in_sizes, int n_in,
                              void* d_out, int out_size)
{
    const float* hid    = (const float*)d_in[0];
    const int*   amask  = (const int*)  d_in[1];
    const int*   labels = (const int*)  d_in[2];
    const float* W      = (const float*)d_in[3];
    const float* bias   = (const float*)d_in[4];
    const float* st     = (const float*)d_in[5];
    const float* et     = (const float*)d_in[6];
    const float* tr     = (const float*)d_in[7];
    float* out = (float*)d_out;

    cudaFuncSetAttribute(emis_kernel,
        cudaFuncAttributeMaxDynamicSharedMemorySize, EMIS_SMEM);

    emis_kernel<<<NROWS / ROWS_PB, EB, EMIS_SMEM>>>(hid, W, bias, out);
    chunk_kernel<<<dim3(NCH, BB), 32>>>(amask, tr);
    combine_kernel<<<BB, 64>>>(amask, labels, st, et, tr, out);
}

// round 6
// speedup vs baseline: 1.8513x; 1.7428x over previous
#include <cuda_runtime.h>
#include <cstdint>

#define BB 64
#define SS 512
#define HH 768
#define LL 9
#define NROWS (BB*SS)
#define NCH 16          // chunks per batch
#define CHL 32          // steps per chunk

static __device__ float g_emis[NROWS * LL];     // natural-log emissions
static __device__ float g_mats[BB * NCH * 84];  // 9x9 linear matrices + scale

#define LOG2E 1.4426950408889634f
#define LN2   0.6931471805599453f

// ---------------------------------------------------------------------------
// Fused kernel: emissions GEMM (register-prefetch pipelined) + per-chunk
// 9x9 transition products. 256 threads, 256 rows/block, 128 blocks.
// Block bx covers batch b = bx/2, timesteps t in [(bx&1)*256, +256),
// i.e. global chunks (bx&1)*8 + w for warps w = 0..7.
// ---------------------------------------------------------------------------
#define EB 256
#define ROWS_PB 256
#define HCH 32
#define NHC (HH / HCH)        // 24 chunks of h
#define XSTR 36               // floats per staged row (32 used + pad, 16B-aligned)
#define OFF_X 0
#define SM_XBUF (ROWS_PB * XSTR)          // 9216 floats
#define OFF_WC SM_XBUF                    // 9216
#define OFF_EM (OFF_WC + LL * HH)         // 9216 + 6912 = 16128
#define EMSTR 10
#define OFF_MK (OFF_EM + ROWS_PB * EMSTR) // 16128 + 2560 = 18688
#define SM_FLOATS (OFF_MK + ROWS_PB)      // 18944 floats
#define FUSED_SMEM (SM_FLOATS * 4)        // 75776 bytes

extern __shared__ float sm[];

__device__ __forceinline__ void rescale3(float& a0, float& a1, float& a2, float& sc)
{
    float mx = fmaxf(fmaxf(a0, a1), a2);
#pragma unroll
    for (int o = 16; o > 0; o >>= 1)
        mx = fmaxf(mx, __shfl_xor_sync(0xFFFFFFFFu, mx, o));
    int ex = (__float_as_int(mx) >> 23) - 127;
    float s = __int_as_float((127 - ex) << 23);
    a0 *= s; a1 *= s; a2 *= s;
    sc += (float)ex;
}

__global__ __launch_bounds__(EB) void fused_kernel(
    const float* __restrict__ hid,
    const float* __restrict__ W,
    const float* __restrict__ bias,
    const int*   __restrict__ mask,
    const float* __restrict__ trans,
    float* __restrict__ out)
{
    const int tid = threadIdx.x;
    const int bx  = blockIdx.x;
    const int r0  = bx * ROWS_PB;
    float* Xs = sm + OFF_X;           // [256][36]
    float* Wc = sm + OFF_WC;          // [9][768]
    float* Em = sm + OFF_EM;          // [256][10]
    int*   Mk = (int*)(sm + OFF_MK);  // [256]

    // each thread's 8 staging slots (row r, h4 group w4), fixed across chunks
    int s_r[8], s_w4[8];
#pragma unroll
    for (int o = 0; o < 8; o++) {
        int f = tid + o * EB;          // 0..2047
        s_r[o] = f >> 3; s_w4[o] = f & 7;
    }

    // ---- stage W (transposed to [j][h]), mask; zero out scalar ----
    for (int idx = tid; idx < HH * LL; idx += EB) {
        int h = idx / LL, j = idx - h * LL;
        Wc[j * HH + h] = W[idx];
    }
    Mk[tid] = mask[r0 + tid];   // row index == b*SS + t
    if (bx == 0 && tid == 0) out[0] = 0.0f;

    float acc[LL];
#pragma unroll
    for (int j = 0; j < LL; j++) acc[j] = bias[j];

    // ---- prologue: load chunk 0 into registers, store to smem ----
    float4 pf[8];
#pragma unroll
    for (int o = 0; o < 8; o++)
        pf[o] = *reinterpret_cast<const float4*>(
            hid + (size_t)(r0 + s_r[o]) * HH + 0 + 4 * s_w4[o]);
#pragma unroll
    for (int o = 0; o < 8; o++)
        *reinterpret_cast<float4*>(Xs + s_r[o] * XSTR + 4 * s_w4[o]) = pf[o];
    __syncthreads();   // chunk 0 staged (also covers Wc / Mk)

    for (int c = 0; c < NHC; c++) {
        // prefetch next chunk into registers (LDG latency hidden by compute)
        if (c + 1 < NHC) {
            const int hc = (c + 1) * HCH;
#pragma unroll
            for (int o = 0; o < 8; o++)
                pf[o] = *reinterpret_cast<const float4*>(
                    hid + (size_t)(r0 + s_r[o]) * HH + hc + 4 * s_w4[o]);
        }

        // compute on chunk c from smem
        const int hc = c * HCH;
        const float* xp = Xs + tid * XSTR;
#pragma unroll
        for (int h4 = 0; h4 < 8; h4++) {
            float4 x = *reinterpret_cast<const float4*>(xp + 4 * h4);
#pragma unroll
            for (int j = 0; j < LL; j++) {
                float4 w = *reinterpret_cast<const float4*>(Wc + j * HH + hc + 4 * h4);
                acc[j] = fmaf(x.x, w.x, fmaf(x.y, w.y,
                         fmaf(x.z, w.z, fmaf(x.w, w.w, acc[j]))));
            }
        }

        if (c + 1 < NHC) {
            __syncthreads();   // all done reading chunk c
#pragma unroll
            for (int o = 0; o < 8; o++)
                *reinterpret_cast<float4*>(Xs + s_r[o] * XSTR + 4 * s_w4[o]) = pf[o];
            __syncthreads();   // chunk c+1 staged
        }
    }

    // ---- store emissions: global (for combine) + smem (for chunk phase) ----
    {
        float* ep = g_emis + (size_t)(r0 + tid) * LL;
#pragma unroll
        for (int j = 0; j < LL; j++) { ep[j] = acc[j]; Em[tid * EMSTR + j] = acc[j]; }
    }
    __syncthreads();

    // ---- chunk phase: warp w computes chunk product for its 32 steps ----
    const int wid  = tid >> 5;
    const int lane = tid & 31;
    const int b    = bx >> 1;
    const int gc   = (bx & 1) * 8 + wid;          // global chunk 0..15

    const int l  = (lane < 27) ? lane : 26;
    const int i  = l / 3;
    const int jb = 3 * (l - 3 * i);

    float ET0[LL], ET1[LL], ET2[LL];
#pragma unroll
    for (int k = 0; k < LL; k++) {
        ET0[k] = __expf(trans[k * LL + jb + 0]);
        ET1[k] = __expf(trans[k * LL + jb + 1]);
        ET2[k] = __expf(trans[k * LL + jb + 2]);
    }

    float a0 = (i == jb + 0) ? 1.0f : 0.0f;
    float a1 = (i == jb + 1) ? 1.0f : 0.0f;
    float a2 = (i == jb + 2) ? 1.0f : 0.0f;
    float sc = 0.0f;

    const int lt0 = wid * CHL;                 // block-local step base
    const int ts  = (gc == 0) ? 1 : 0;         // skip t=0 globally

    float e0 = Em[(lt0 + ts) * EMSTR + jb];
    float e1 = Em[(lt0 + ts) * EMSTR + jb + 1];
    float e2 = Em[(lt0 + ts) * EMSTR + jb + 2];
    int mk = Mk[lt0 + ts];
    int cnt = 0;

    for (int t = ts; t < CHL; t++) {
        float f0 = __expf(e0), f1 = __expf(e1), f2 = __expf(e2);
        int m = mk;
        if (t + 1 < CHL) {
            e0 = Em[(lt0 + t + 1) * EMSTR + jb];
            e1 = Em[(lt0 + t + 1) * EMSTR + jb + 1];
            e2 = Em[(lt0 + t + 1) * EMSTR + jb + 2];
            mk = Mk[lt0 + t + 1];
        }
        float r0s = __shfl_sync(0xFFFFFFFFu, a0, 3*i    );
        float r1s = __shfl_sync(0xFFFFFFFFu, a1, 3*i    );
        float r2s = __shfl_sync(0xFFFFFFFFu, a2, 3*i    );
        float r3s = __shfl_sync(0xFFFFFFFFu, a0, 3*i + 1);
        float r4s = __shfl_sync(0xFFFFFFFFu, a1, 3*i + 1);
        float r5s = __shfl_sync(0xFFFFFFFFu, a2, 3*i + 1);
        float r6s = __shfl_sync(0xFFFFFFFFu, a0, 3*i + 2);
        float r7s = __shfl_sync(0xFFFFFFFFu, a1, 3*i + 2);
        float r8s = __shfl_sync(0xFFFFFFFFu, a2, 3*i + 2);

        float n0 = r0s*ET0[0] + r1s*ET0[1]; n0 += r2s*ET0[2] + r3s*ET0[3];
        n0 += r4s*ET0[4] + r5s*ET0[5];      n0 += r6s*ET0[6] + r7s*ET0[7] + r8s*ET0[8];
        float n1 = r0s*ET1[0] + r1s*ET1[1]; n1 += r2s*ET1[2] + r3s*ET1[3];
        n1 += r4s*ET1[4] + r5s*ET1[5];      n1 += r6s*ET1[6] + r7s*ET1[7] + r8s*ET1[8];
        float n2 = r0s*ET2[0] + r1s*ET2[1]; n2 += r2s*ET2[2] + r3s*ET2[3];
        n2 += r4s*ET2[4] + r5s*ET2[5];      n2 += r6s*ET2[6] + r7s*ET2[7] + r8s*ET2[8];
        n0 *= f0; n1 *= f1; n2 *= f2;

        a0 = m ? n0 : a0;  a1 = m ? n1 : a1;  a2 = m ? n2 : a2;
        if (((++cnt) & 7) == 0) rescale3(a0, a1, a2, sc);
    }

    rescale3(a0, a1, a2, sc);

    float* mb = g_mats + (size_t)(b * NCH + gc) * 84;
    if (lane < 27) {
        mb[i * LL + jb + 0] = a0;
        mb[i * LL + jb + 1] = a1;
        mb[i * LL + jb + 2] = a2;
    }
    if (lane == 0) mb[81] = sc;
}

// ---------------------------------------------------------------------------
// Kernel 2: per-batch fold of 16 chunk matrices (warp 0) + numerator (warp 1).
// ---------------------------------------------------------------------------
__global__ __launch_bounds__(64) void combine_kernel(
    const int*   __restrict__ mask,
    const int*   __restrict__ labels,
    const float* __restrict__ start_trans,
    const float* __restrict__ end_trans,
    const float* __restrict__ trans,
    float* __restrict__ out)
{
    __shared__ float sh_denom, sh_num;
    const int b = blockIdx.x;
    const int wid = threadIdx.x >> 5;
    const int lane = threadIdx.x & 31;

    if (wid == 0) {
        const int j = (lane < LL) ? lane : (LL - 1);
        const float* em = g_emis + (size_t)b * SS * LL;

        float a = start_trans[j] + em[j];
        float mx = a;
#pragma unroll
        for (int o = 16; o > 0; o >>= 1)
            mx = fmaxf(mx, __shfl_xor_sync(0xFFFFFFFFu, mx, o));
        float v  = __expf(a - mx);
        float sc = mx * LOG2E;

        for (int c = 0; c < NCH; c++) {
            const float* mb = g_mats + (size_t)(b * NCH + c) * 84;
            float col[LL];
#pragma unroll
            for (int i2 = 0; i2 < LL; i2++) col[i2] = mb[i2 * LL + j];
            float msc = mb[81];

            float n = 0.0f;
#pragma unroll
            for (int i2 = 0; i2 < LL; i2++) {
                float vv = __shfl_sync(0xFFFFFFFFu, v, i2);
                n = fmaf(vv, col[i2], n);
            }
            sc += msc;
            float m2 = n;
#pragma unroll
            for (int o = 16; o > 0; o >>= 1)
                m2 = fmaxf(m2, __shfl_xor_sync(0xFFFFFFFFu, m2, o));
            int ex = (__float_as_int(m2) >> 23) - 127;
            n *= __int_as_float((127 - ex) << 23);
            sc += (float)ex;
            v = n;
        }

        float x = v * __expf(end_trans[j]);
        if (lane >= LL) x = 0.0f;
#pragma unroll
        for (int o = 16; o > 0; o >>= 1)
            x += __shfl_xor_sync(0xFFFFFFFFu, x, o);
        if (lane == 0) sh_denom = (sc + __log2f(x)) * LN2;
    }
    else {  // numerator
        float part = 0.0f;
        int   cnt  = 0;
        for (int s0 = lane; s0 < SS; s0 += 32) {
            int   mk = mask[b * SS + s0];
            cnt += mk;
            int   lb = labels[b * SS + s0];
            float et = g_emis[((size_t)b * SS + s0) * LL + lb];
            if (s0 == 0) {
                part += start_trans[lb] + et;
            } else {
                int lp = labels[b * SS + s0 - 1];
                part += (trans[lp * LL + lb] + et) * (float)mk;
            }
        }
#pragma unroll
        for (int o = 16; o > 0; o >>= 1) {
            part += __shfl_down_sync(0xFFFFFFFFu, part, o);
            cnt  += __shfl_down_sync(0xFFFFFFFFu, cnt,  o);
        }
        if (lane == 0) {
            int li = cnt - 1; if (li < 0) li = 0;
            int lt = labels[b * SS + li];
            sh_num = part + end_trans[lt];
        }
    }

    __syncthreads();
    if (threadIdx.x == 0) atomicAdd(out, sh_denom - sh_num);
}

// ---------------------------------------------------------------------------
extern "C" void kernel_launch(void* const* d_in, const int* in_sizes, int n_in,
                              void* d_out, int out_size)
{
    const float* hid    = (const float*)d_in[0];
    const int*   amask  = (const int*)  d_in[1];
    const int*   labels = (const int*)  d_in[2];
    const float* W      = (const float*)d_in[3];
    const float* bias   = (const float*)d_in[4];
    const float* st     = (const float*)d_in[5];
    const float* et     = (const float*)d_in[6];
    const float* tr     = (const float*)d_in[7];
    float* out = (float*)d_out;

    cudaFuncSetAttribute(fused_kernel,
        cudaFuncAttributeMaxDynamicSharedMemorySize, FUSED_SMEM);

    fused_kernel<<<NROWS / ROWS_PB, EB, FUSED_SMEM>>>(hid, W, bias, amask, tr, out);
    combine_kernel<<<BB, 64>>>(amask, labels, st, et, tr, out);
}